// round 3
// baseline (speedup 1.0000x reference)
#include <cuda_runtime.h>
#include <math.h>

#define NB 64
#define NT 512
#define NV 512
#define NH 256
#define NO 512
#define MR (NB * NT)   // 32768 rows

// Scratch (allocation-free rule: __device__ globals)
__device__ float g_xproj[(size_t)MR * NH];   // x@W_ih^T + b_ih + b_hh
__device__ float g_hidden[(size_t)MR * NH];  // min(relu(h),1)

typedef unsigned long long ull;

__device__ __forceinline__ ull fma2(ull a, ull b, ull c) {
    ull d;
    asm("fma.rn.f32x2 %0, %1, %2, %3;" : "=l"(d) : "l"(a), "l"(b), "l"(c));
    return d;
}
__device__ __forceinline__ ull pack2(float lo, float hi) {
    ull r;
    unsigned int l = __float_as_uint(lo), h = __float_as_uint(hi);
    asm("mov.b64 %0, {%1, %2};" : "=l"(r) : "r"(l), "r"(h));
    return r;
}
__device__ __forceinline__ float2 unpack2(ull v) {
    unsigned int l, h;
    asm("mov.b64 {%0, %1}, %2;" : "=r"(l), "=r"(h) : "l"(v));
    return make_float2(__uint_as_float(l), __uint_as_float(h));
}

// ---------------------------------------------------------------------------
// GEMM: C[m,n] = epi( sum_k A[m,k]*Bw[n,k] + bias )   (both operands K-major)
// BM=BN=128, BK=16, 256 threads, 8x8 micro-tile via f32x2 packed FMA.
// EPI==0: + bias1[n] + bias2[n]      EPI==1: sigmoid(x + bias1[n])
// ---------------------------------------------------------------------------
template<int EPI>
__global__ void __launch_bounds__(256, 2)
gemm_nt(const float* __restrict__ A, const float* __restrict__ Bw,
        const float* __restrict__ bias1, const float* __restrict__ bias2,
        float* __restrict__ C, int M, int N, int K)
{
    __shared__ __align__(16) float As[16][132];
    __shared__ __align__(16) float Bs[16][132];
    const int tid = threadIdx.x;
    const int m0 = blockIdx.y << 7;
    const int n0 = blockIdx.x << 7;
    const int ar = tid >> 2;          // 0..63
    const int ac = (tid & 3) << 2;    // 0,4,8,12
    const float* Ag = A  + (size_t)(m0 + ar) * K + ac;
    const float* Bg = Bw + (size_t)(n0 + ar) * K + ac;
    const int tm = tid >> 4;          // 0..15 (row group of 8)
    const int tn = tid & 15;          // 0..15 (col group: tn*4 and tn*4+64)

    ull acc[4][8];
#pragma unroll
    for (int i = 0; i < 4; i++)
#pragma unroll
        for (int j = 0; j < 8; j++) acc[i][j] = 0ull;

    for (int k0 = 0; k0 < K; k0 += 16) {
        float4 a0 = *(const float4*)(Ag);
        float4 a1 = *(const float4*)(Ag + (size_t)64 * K);
        float4 b0 = *(const float4*)(Bg);
        float4 b1 = *(const float4*)(Bg + (size_t)64 * K);
        __syncthreads();
        As[ac + 0][ar]      = a0.x; As[ac + 1][ar]      = a0.y;
        As[ac + 2][ar]      = a0.z; As[ac + 3][ar]      = a0.w;
        As[ac + 0][ar + 64] = a1.x; As[ac + 1][ar + 64] = a1.y;
        As[ac + 2][ar + 64] = a1.z; As[ac + 3][ar + 64] = a1.w;
        Bs[ac + 0][ar]      = b0.x; Bs[ac + 1][ar]      = b0.y;
        Bs[ac + 2][ar]      = b0.z; Bs[ac + 3][ar]      = b0.w;
        Bs[ac + 0][ar + 64] = b1.x; Bs[ac + 1][ar + 64] = b1.y;
        Bs[ac + 2][ar + 64] = b1.z; Bs[ac + 3][ar + 64] = b1.w;
        __syncthreads();
#pragma unroll
        for (int k = 0; k < 16; k++) {
            ulonglong2 aA = *(const ulonglong2*)&As[k][tm * 8];
            ulonglong2 aB = *(const ulonglong2*)&As[k][tm * 8 + 4];
            float4 bA = *(const float4*)&Bs[k][tn * 4];
            float4 bB = *(const float4*)&Bs[k][tn * 4 + 64];
            ull a2[4] = { aA.x, aA.y, aB.x, aB.y };
            ull bb[8] = { pack2(bA.x, bA.x), pack2(bA.y, bA.y),
                          pack2(bA.z, bA.z), pack2(bA.w, bA.w),
                          pack2(bB.x, bB.x), pack2(bB.y, bB.y),
                          pack2(bB.z, bB.z), pack2(bB.w, bB.w) };
#pragma unroll
            for (int j = 0; j < 8; j++)
#pragma unroll
                for (int i = 0; i < 4; i++)
                    acc[i][j] = fma2(a2[i], bb[j], acc[i][j]);
        }
        Ag += 16; Bg += 16;
    }

    float bv[8];
#pragma unroll
    for (int j = 0; j < 4; j++) {
        bv[j]     = bias1[n0 + tn * 4 + j];
        bv[4 + j] = bias1[n0 + tn * 4 + 64 + j];
    }
    if (EPI == 0) {
#pragma unroll
        for (int j = 0; j < 4; j++) {
            bv[j]     += bias2[n0 + tn * 4 + j];
            bv[4 + j] += bias2[n0 + tn * 4 + 64 + j];
        }
    }
#pragma unroll
    for (int i2 = 0; i2 < 4; i2++) {
        float2 v[8];
#pragma unroll
        for (int j = 0; j < 8; j++) v[j] = unpack2(acc[i2][j]);
#pragma unroll
        for (int half = 0; half < 2; half++) {
            int m = m0 + tm * 8 + i2 * 2 + half;
            float r[8];
#pragma unroll
            for (int j = 0; j < 8; j++) {
                float x = (half ? v[j].y : v[j].x) + bv[j];
                if (EPI == 1) x = 1.0f / (1.0f + expf(-x));
                r[j] = x;
            }
            *(float4*)&C[(size_t)m * N + n0 + tn * 4]      = make_float4(r[0], r[1], r[2], r[3]);
            *(float4*)&C[(size_t)m * N + n0 + tn * 4 + 64] = make_float4(r[4], r[5], r[6], r[7]);
        }
    }
}

// ---------------------------------------------------------------------------
// Recurrence: 64 clusters of 2 CTAs, one batch element per cluster.
// CTA rank r owns output rows [r*128, r*128+128). W_hh half lives in REGISTERS
// (thread t: row = r*128 + (t&127), j-range = (t>>7)*128 .. +128, as 64 ull).
// h (256 floats) is replicated in each CTA's smem; the owner CTA writes its
// half locally AND to the peer via st.shared::cluster; barrier.cluster per step.
// ---------------------------------------------------------------------------
__global__ void __cluster_dims__(2, 1, 1) __launch_bounds__(256, 1)
rnn_scan(const float* __restrict__ W_hh, const float* __restrict__ prev,
         float* __restrict__ hn_out)
{
    __shared__ __align__(16) float h_sh[2][NH];
    __shared__ float red[128];
    const int tid = threadIdx.x;
    const int b = blockIdx.x >> 1;
    unsigned int rank;
    asm("mov.u32 %0, %%cluster_ctarank;" : "=r"(rank));
    const int jh = tid >> 7;            // which j-half this thread reduces
    const int il = tid & 127;           // local row
    const int col = (int)rank * 128 + il;  // W row / output column

    // Load this thread's 128 weights as 64 packed f32x2 (bit-identical layout)
    ull w2[64];
    {
        const ull* wrow = (const ull*)(W_hh + (size_t)col * NH + jh * 128);
#pragma unroll
        for (int q = 0; q < 64; q++) w2[q] = wrow[q];
    }

    // Init h0
    h_sh[0][tid] = prev[b * NH + tid];
    __syncthreads();

    // Remote (peer CTA) addresses for both h buffers
    unsigned int loc0 = (unsigned int)__cvta_generic_to_shared(&h_sh[0][col]);
    unsigned int loc1 = (unsigned int)__cvta_generic_to_shared(&h_sh[1][col]);
    unsigned int peer = rank ^ 1u;
    unsigned int rem0, rem1;
    asm("mapa.shared::cluster.u32 %0, %1, %2;" : "=r"(rem0) : "r"(loc0), "r"(peer));
    asm("mapa.shared::cluster.u32 %0, %1, %2;" : "=r"(rem1) : "r"(loc1), "r"(peer));

    const float* xrow  = g_xproj  + ((size_t)b * NT) * NH + col;
    float*       hidro = g_hidden + ((size_t)b * NT) * NH + col;
    float xp_next = (jh == 0) ? xrow[0] : 0.0f;

    int p = 0;
    for (int t = 0; t < NT; t++) {
        float xp = xp_next;
        if (jh == 0 && t + 1 < NT) xp_next = xrow[(size_t)(t + 1) * NH];  // prefetch

        const ulonglong2* h4 = (const ulonglong2*)&h_sh[p][jh * 128];
        ull aA = 0ull, aB = 0ull;
#pragma unroll
        for (int q = 0; q < 32; q++) {
            ulonglong2 hv = h4[q];
            aA = fma2(w2[2 * q],     hv.x, aA);
            aB = fma2(w2[2 * q + 1], hv.y, aB);
        }
        float2 fa = unpack2(aA), fb = unpack2(aB);
        float acc = (fa.x + fa.y) + (fb.x + fb.y);

        if (jh) red[il] = acc;
        __syncthreads();
        if (jh == 0) {
            float h = fmaxf(acc + red[il] + xp, 0.0f);
            h_sh[p ^ 1][col] = h;                       // local copy
            unsigned int radr = p ? rem0 : rem1;        // peer copy (buffer p^1)
            unsigned int hb = __float_as_uint(h);
            asm volatile("st.shared::cluster.b32 [%0], %1;" :: "r"(radr), "r"(hb) : "memory");
            hidro[(size_t)t * NH] = fminf(h, 1.0f);     // capped lrelu (h>=0)
            if (t == NT - 1) hn_out[b * NH + col] = h;
        }
        // release local+remote writes, acquire peer's
        asm volatile("barrier.cluster.arrive.aligned;" ::: "memory");
        asm volatile("barrier.cluster.wait.aligned;" ::: "memory");
        p ^= 1;
    }
}

// ---------------------------------------------------------------------------
extern "C" void kernel_launch(void* const* d_in, const int* in_sizes, int n_in,
                              void* d_out, int out_size)
{
    const float* sentence = (const float*)d_in[0];
    const float* prev     = (const float*)d_in[1];
    const float* W_ih     = (const float*)d_in[2];
    const float* b_ih     = (const float*)d_in[3];
    const float* W_hh     = (const float*)d_in[4];
    const float* b_hh     = (const float*)d_in[5];
    const float* W_out    = (const float*)d_in[6];
    const float* b_out    = (const float*)d_in[7];
    float* out = (float*)d_out;

    float* xproj = nullptr;
    float* hidden = nullptr;
    cudaGetSymbolAddress((void**)&xproj, g_xproj);
    cudaGetSymbolAddress((void**)&hidden, g_hidden);

    // Phase 1: x_proj = sentence @ W_ih^T + (b_ih + b_hh)
    gemm_nt<0><<<dim3(NH / 128, MR / 128), 256>>>(sentence, W_ih, b_ih, b_hh,
                                                  xproj, MR, NH, NV);
    // Phase 2: sequential scan; writes g_hidden and h_n (tail of d_out)
    rnn_scan<<<NB * 2, 256>>>(W_hh, prev, out + (size_t)MR * NO);
    // Phase 3: tags = sigmoid(hidden @ W_out^T + b_out)
    gemm_nt<1><<<dim3(NO / 128, MR / 128), 256>>>(hidden, W_out, b_out, nullptr,
                                                  out, MR, NO, NH);
}